// round 15
// baseline (speedup 1.0000x reference)
#include <cuda_runtime.h>
#include <cstdint>
#include <math.h>

// ---------------------------------------------------------------------------
// LOUPE sampler (R12 structure — best measured config; apply blockDim 128).
//  Host: threefry split-chain (data-independent) -> 32 candidate sub-keys.
//  mask_kernel : 32 blocks x 320 threads, one candidate each; last-block
//    ticket selects first accepted candidate -> d_mask (seq. fallback).
//    PDL trigger at entry so apply's launch overlaps execution.
//  apply_mask  : PDL secondary, 1 float4/thread flat indexing (FROZEN
//    access pattern); 128-thread CTAs for maximal CTA-level concurrency.
// Output: [masked_kspace 256*2*320*320 f32][mask_full 256*1*320*320 f32]
// ---------------------------------------------------------------------------

#define SLOPE  5.0f
#define LN     320
#define NPROBE 32

struct SubKeys {
    uint2 s[NPROBE];   // sub-key for candidate i
    uint2 tail;        // key state after NPROBE splits (fallback chain)
};

__device__ float    d_mask[LN];
__device__ float    d_xs[LN];
__device__ int      d_cnt[NPROBE];
__device__ uint32_t d_words[NPROBE][10];
__device__ int      d_ticket = 0;     // reset by finalizer each run

// --- threefry2x32, 20 rounds (JAX), host+device ---
__host__ __device__ __forceinline__ uint32_t rotl32(uint32_t v, int d) {
    return (v << d) | (v >> (32 - d));
}

__host__ __device__ __forceinline__ void threefry2x32(
    uint32_t k0, uint32_t k1, uint32_t c0, uint32_t c1,
    uint32_t& o0, uint32_t& o1) {
    uint32_t k2 = k0 ^ k1 ^ 0x1BD11BDAu;
    uint32_t x0 = c0 + k0;
    uint32_t x1 = c1 + k1;
#define TF_ROUND(r) { x0 += x1; x1 = rotl32(x1, (r)); x1 ^= x0; }
    TF_ROUND(13) TF_ROUND(15) TF_ROUND(26) TF_ROUND(6)
    x0 += k1; x1 += k2 + 1u;
    TF_ROUND(17) TF_ROUND(29) TF_ROUND(16) TF_ROUND(24)
    x0 += k2; x1 += k0 + 2u;
    TF_ROUND(13) TF_ROUND(15) TF_ROUND(26) TF_ROUND(6)
    x0 += k0; x1 += k1 + 3u;
    TF_ROUND(17) TF_ROUND(29) TF_ROUND(16) TF_ROUND(24)
    x0 += k1; x1 += k2 + 4u;
    TF_ROUND(13) TF_ROUND(15) TF_ROUND(26) TF_ROUND(6)
    x0 += k2; x1 += k0 + 5u;
#undef TF_ROUND
    o0 = x0; o1 = x1;
}

__device__ __forceinline__ float bits_to_uniform(uint32_t b) {
    return __uint_as_float((b >> 9) | 0x3f800000u) - 1.0f;
}

// ---------------------------------------------------------------------------
// mask_kernel: 32 blocks x 320 threads. Block b evaluates candidate b; the
// last block to finish (atomic ticket) performs selection + emission.
// JAX partitionable threefry: bits(key,j) = x0^x1 of TF(key, 0, j).
// mean(rescaled) == sparsity analytically (validated rel_err 0.0).
// ---------------------------------------------------------------------------
__global__ void __launch_bounds__(LN) mask_kernel(
    const float* __restrict__ logits, const float* __restrict__ sparsity_p,
    SubKeys subs) {
    __shared__ float wsum[10];
    __shared__ float sh_xbar;
    __shared__ int   sh_last, sh_sel;

    cudaTriggerProgrammaticLaunchCompletion();

    const int tid  = threadIdx.x;
    const int wid  = tid >> 5;
    const int lane = tid & 31;
    const int b    = blockIdx.x;

    const float sparsity = __ldg(sparsity_p);

    float s = 1.0f / (1.0f + expf(-SLOPE * logits[tid]));

    // block reduce: xbar
    float a = s;
    for (int o = 16; o > 0; o >>= 1) a += __shfl_down_sync(0xffffffffu, a, o);
    if (lane == 0) wsum[wid] = a;
    __syncthreads();
    if (wid == 0) {
        float t = (lane < 10) ? wsum[lane] : 0.0f;
        for (int o = 8; o > 0; o >>= 1) t += __shfl_down_sync(0xffffffffu, t, o);
        if (lane == 0) sh_xbar = t / (float)LN;
    }
    __syncthreads();

    // rescale; xm == sparsity analytically
    const float xbar = sh_xbar;
    const float r    = sparsity / xbar;
    const float beta = (1.0f - sparsity) / (1.0f - xbar);
    const float x    = (r <= 1.0f) ? (s * r) : (1.0f - (1.0f - s) * beta);
    if (b == 0) d_xs[tid] = x;                 // for fallback
    const float xm  = sparsity;
    const float tol = 1e-3f + 1e-5f * fabsf(xm);

    // draw candidate b
    const uint2 sub = subs.s[b];
    uint32_t u, v;
    threefry2x32(sub.x, sub.y, 0u, (uint32_t)tid, u, v);
    const int pred = x > bits_to_uniform(u ^ v);

    const uint32_t w = __ballot_sync(0xffffffffu, pred);
    if (lane == 0) d_words[b][wid] = w;

    const int c = __syncthreads_count(pred);
    if (tid == 0) d_cnt[b] = c;

    // ---- last-block ticket: finalizer ----
    if (tid == 0) {
        __threadfence();                       // publish d_words/d_cnt/d_xs
        int t = atomicAdd(&d_ticket, 1);
        sh_last = (t == NPROBE - 1) ? 1 : 0;
        if (sh_last) d_ticket = 0;             // reset for next graph replay
    }
    __syncthreads();
    if (!sh_last) return;

    // selection
    if (tid == 0) {
        int sel = -1;
        for (int i = 0; i < NPROBE; i++) {
            float m = (float)(*(volatile int*)&d_cnt[i]) / (float)LN;
            if (fabsf(m - xm) <= tol) { sel = i; break; }
        }
        sh_sel = sel;
    }
    __syncthreads();
    const int sel = sh_sel;

    float vout;
    if (sel >= 0) {
        uint32_t ww = *(volatile uint32_t*)&d_words[sel][wid];
        vout = ((ww >> lane) & 1u) ? 1.0f : 0.0f;
    } else {
        // fallback (rare): continue sequential split chain from subs.tail
        __shared__ uint32_t key0, key1, sub0, sub1;
        if (tid == 0) { key0 = subs.tail.x; key1 = subs.tail.y; }
        __syncthreads();
        const float xl = *(volatile float*)&d_xs[tid];
        bool res = false;
        for (int iter = 0; iter < 100000; ++iter) {
            if (tid == 0) {   // split(key): new=TF(key,0,0), sub=TF(key,0,1)
                uint32_t nk0, nk1, ns0, ns1;
                threefry2x32(key0, key1, 0u, 0u, nk0, nk1);
                threefry2x32(key0, key1, 0u, 1u, ns0, ns1);
                key0 = nk0; key1 = nk1;
                sub0 = ns0; sub1 = ns1;
            }
            __syncthreads();
            uint32_t uu, vv;
            threefry2x32(sub0, sub1, 0u, (uint32_t)tid, uu, vv);
            res = xl > bits_to_uniform(uu ^ vv);
            int cc = __syncthreads_count(res ? 1 : 0);
            float m = (float)cc / (float)LN;
            if (fabsf(m - xm) <= tol) break;
        }
        vout = res ? 1.0f : 0.0f;
    }

    if (tid == 0 || tid == LN - 1) vout = 1.0f;
    d_mask[tid] = vout;
}

// ---------------------------------------------------------------------------
// apply (PDL secondary): flat 1 float4/thread (FROZEN pattern). Index math
// before grid sync; 128-thread CTAs.
// ---------------------------------------------------------------------------
__global__ void __launch_bounds__(128) apply_mask_kernel(
    const float4* __restrict__ ksp, float4* __restrict__ out,
    int n4m, int n4tot) {
    const int idx = blockIdx.x * blockDim.x + threadIdx.x;

    // independent prologue (overlaps mask execution)
    const bool in_ksp = idx < n4m;
    const int  row    = in_ksp ? ((idx / 80) % LN)
                               : (((idx - n4m) / 80) % LN);

    // wait for mask_kernel's writes to be visible
    cudaGridDependencySynchronize();

    if (idx >= n4tot) return;
    const float m = d_mask[row];       // exactly 0.0f or 1.0f
    if (in_ksp) {
        if (m != 0.0f) {
            __stcs(&out[idx], __ldcs(&ksp[idx]));
        } else {
            __stcs(&out[idx], make_float4(0.f, 0.f, 0.f, 0.f));
        }
    } else {
        __stcs(&out[idx], make_float4(m, m, m, m));
    }
}

extern "C" void kernel_launch(void* const* d_in, const int* in_sizes, int n_in,
                              void* d_out, int out_size) {
    const float* kspace   = (const float*)d_in[0];  // (256,2,320,320)
    const float* sparsity = (const float*)d_in[1];  // scalar
    const float* logits   = (const float*)d_in[2];  // (320,)

    // Host-side threefry split chain (independent of device inputs).
    // JAX partitionable split: new_key = TF(key,0,0), sub = TF(key,0,1).
    SubKeys subs;
    {
        uint32_t k0 = 0u, k1 = 42u;   // jax.random.key(42)
        for (int i = 0; i < NPROBE; i++) {
            uint32_t s0, s1, n0, n1;
            threefry2x32(k0, k1, 0u, 1u, s0, s1);
            threefry2x32(k0, k1, 0u, 0u, n0, n1);
            subs.s[i] = make_uint2(s0, s1);
            k0 = n0; k1 = n1;
        }
        subs.tail = make_uint2(k0, k1);
    }

    mask_kernel<<<NPROBE, LN>>>(logits, sparsity, subs);

    int n4m   = in_sizes[0] / 4;
    int n4tot = out_size / 4;
    int threads = 128;
    int blocks  = (n4tot + threads - 1) / threads;

    cudaLaunchConfig_t cfg = {};
    cfg.gridDim  = dim3((unsigned)blocks, 1, 1);
    cfg.blockDim = dim3((unsigned)threads, 1, 1);
    cfg.dynamicSmemBytes = 0;
    cfg.stream = 0;
    cudaLaunchAttribute attr[1];
    attr[0].id = cudaLaunchAttributeProgrammaticStreamSerialization;
    attr[0].val.programmaticStreamSerializationAllowed = 1;
    cfg.attrs = attr;
    cfg.numAttrs = 1;
    cudaLaunchKernelEx(&cfg, apply_mask_kernel,
                       (const float4*)kspace, (float4*)d_out, n4m, n4tot);
}

// round 16
// speedup vs baseline: 1.4238x; 1.4238x over previous
#include <cuda_runtime.h>
#include <cstdint>
#include <math.h>

// ---------------------------------------------------------------------------
// LOUPE sampler — converged configuration (best measured: 63.07 us).
//  Host: threefry split-chain (data-independent) -> 32 candidate sub-keys.
//  mask_kernel : 32 blocks x 320 threads, one candidate each; last-block
//    ticket selects first accepted candidate -> d_mask (seq. fallback).
//    PDL trigger at entry so apply's launch overlaps execution.
//  apply_mask  : PDL secondary, 256 thr/CTA, 1 float4/thread flat indexing
//    (measured optimum across 128/256/512 and loop variants), streaming
//    hints, load-skip on zero-mask lines (75% of read traffic eliminated).
// Output: [masked_kspace 256*2*320*320 f32][mask_full 256*1*320*320 f32]
// ---------------------------------------------------------------------------

#define SLOPE  5.0f
#define LN     320
#define NPROBE 32

struct SubKeys {
    uint2 s[NPROBE];   // sub-key for candidate i
    uint2 tail;        // key state after NPROBE splits (fallback chain)
};

__device__ float    d_mask[LN];
__device__ float    d_xs[LN];
__device__ int      d_cnt[NPROBE];
__device__ uint32_t d_words[NPROBE][10];
__device__ int      d_ticket = 0;     // reset by finalizer each run

// --- threefry2x32, 20 rounds (JAX), host+device ---
__host__ __device__ __forceinline__ uint32_t rotl32(uint32_t v, int d) {
    return (v << d) | (v >> (32 - d));
}

__host__ __device__ __forceinline__ void threefry2x32(
    uint32_t k0, uint32_t k1, uint32_t c0, uint32_t c1,
    uint32_t& o0, uint32_t& o1) {
    uint32_t k2 = k0 ^ k1 ^ 0x1BD11BDAu;
    uint32_t x0 = c0 + k0;
    uint32_t x1 = c1 + k1;
#define TF_ROUND(r) { x0 += x1; x1 = rotl32(x1, (r)); x1 ^= x0; }
    TF_ROUND(13) TF_ROUND(15) TF_ROUND(26) TF_ROUND(6)
    x0 += k1; x1 += k2 + 1u;
    TF_ROUND(17) TF_ROUND(29) TF_ROUND(16) TF_ROUND(24)
    x0 += k2; x1 += k0 + 2u;
    TF_ROUND(13) TF_ROUND(15) TF_ROUND(26) TF_ROUND(6)
    x0 += k0; x1 += k1 + 3u;
    TF_ROUND(17) TF_ROUND(29) TF_ROUND(16) TF_ROUND(24)
    x0 += k1; x1 += k2 + 4u;
    TF_ROUND(13) TF_ROUND(15) TF_ROUND(26) TF_ROUND(6)
    x0 += k2; x1 += k0 + 5u;
#undef TF_ROUND
    o0 = x0; o1 = x1;
}

__device__ __forceinline__ float bits_to_uniform(uint32_t b) {
    return __uint_as_float((b >> 9) | 0x3f800000u) - 1.0f;
}

// ---------------------------------------------------------------------------
// mask_kernel: 32 blocks x 320 threads. Block b evaluates candidate b; the
// last block to finish (atomic ticket) performs selection + emission.
// JAX partitionable threefry: bits(key,j) = x0^x1 of TF(key, 0, j).
// mean(rescaled) == sparsity analytically (validated rel_err 0.0).
// ---------------------------------------------------------------------------
__global__ void __launch_bounds__(LN) mask_kernel(
    const float* __restrict__ logits, const float* __restrict__ sparsity_p,
    SubKeys subs) {
    __shared__ float wsum[10];
    __shared__ float sh_xbar;
    __shared__ int   sh_last, sh_sel;

    cudaTriggerProgrammaticLaunchCompletion();

    const int tid  = threadIdx.x;
    const int wid  = tid >> 5;
    const int lane = tid & 31;
    const int b    = blockIdx.x;

    const float sparsity = __ldg(sparsity_p);

    float s = 1.0f / (1.0f + expf(-SLOPE * logits[tid]));

    // block reduce: xbar
    float a = s;
    for (int o = 16; o > 0; o >>= 1) a += __shfl_down_sync(0xffffffffu, a, o);
    if (lane == 0) wsum[wid] = a;
    __syncthreads();
    if (wid == 0) {
        float t = (lane < 10) ? wsum[lane] : 0.0f;
        for (int o = 8; o > 0; o >>= 1) t += __shfl_down_sync(0xffffffffu, t, o);
        if (lane == 0) sh_xbar = t / (float)LN;
    }
    __syncthreads();

    // rescale; xm == sparsity analytically
    const float xbar = sh_xbar;
    const float r    = sparsity / xbar;
    const float beta = (1.0f - sparsity) / (1.0f - xbar);
    const float x    = (r <= 1.0f) ? (s * r) : (1.0f - (1.0f - s) * beta);
    if (b == 0) d_xs[tid] = x;                 // for fallback
    const float xm  = sparsity;
    const float tol = 1e-3f + 1e-5f * fabsf(xm);

    // draw candidate b
    const uint2 sub = subs.s[b];
    uint32_t u, v;
    threefry2x32(sub.x, sub.y, 0u, (uint32_t)tid, u, v);
    const int pred = x > bits_to_uniform(u ^ v);

    const uint32_t w = __ballot_sync(0xffffffffu, pred);
    if (lane == 0) d_words[b][wid] = w;

    const int c = __syncthreads_count(pred);
    if (tid == 0) d_cnt[b] = c;

    // ---- last-block ticket: finalizer ----
    if (tid == 0) {
        __threadfence();                       // publish d_words/d_cnt/d_xs
        int t = atomicAdd(&d_ticket, 1);
        sh_last = (t == NPROBE - 1) ? 1 : 0;
        if (sh_last) d_ticket = 0;             // reset for next graph replay
    }
    __syncthreads();
    if (!sh_last) return;

    // selection
    if (tid == 0) {
        int sel = -1;
        for (int i = 0; i < NPROBE; i++) {
            float m = (float)(*(volatile int*)&d_cnt[i]) / (float)LN;
            if (fabsf(m - xm) <= tol) { sel = i; break; }
        }
        sh_sel = sel;
    }
    __syncthreads();
    const int sel = sh_sel;

    float vout;
    if (sel >= 0) {
        uint32_t ww = *(volatile uint32_t*)&d_words[sel][wid];
        vout = ((ww >> lane) & 1u) ? 1.0f : 0.0f;
    } else {
        // fallback (rare): continue sequential split chain from subs.tail
        __shared__ uint32_t key0, key1, sub0, sub1;
        if (tid == 0) { key0 = subs.tail.x; key1 = subs.tail.y; }
        __syncthreads();
        const float xl = *(volatile float*)&d_xs[tid];
        bool res = false;
        for (int iter = 0; iter < 100000; ++iter) {
            if (tid == 0) {   // split(key): new=TF(key,0,0), sub=TF(key,0,1)
                uint32_t nk0, nk1, ns0, ns1;
                threefry2x32(key0, key1, 0u, 0u, nk0, nk1);
                threefry2x32(key0, key1, 0u, 1u, ns0, ns1);
                key0 = nk0; key1 = nk1;
                sub0 = ns0; sub1 = ns1;
            }
            __syncthreads();
            uint32_t uu, vv;
            threefry2x32(sub0, sub1, 0u, (uint32_t)tid, uu, vv);
            res = xl > bits_to_uniform(uu ^ vv);
            int cc = __syncthreads_count(res ? 1 : 0);
            float m = (float)cc / (float)LN;
            if (fabsf(m - xm) <= tol) break;
        }
        vout = res ? 1.0f : 0.0f;
    }

    if (tid == 0 || tid == LN - 1) vout = 1.0f;
    d_mask[tid] = vout;
}

// ---------------------------------------------------------------------------
// apply (PDL secondary): flat 1 float4/thread, 256 thr/CTA (measured
// optimum). Index math before grid sync; streaming hints; load-skip.
// ---------------------------------------------------------------------------
__global__ void __launch_bounds__(256) apply_mask_kernel(
    const float4* __restrict__ ksp, float4* __restrict__ out,
    int n4m, int n4tot) {
    const int idx = blockIdx.x * blockDim.x + threadIdx.x;

    // independent prologue (overlaps mask execution)
    const bool in_ksp = idx < n4m;
    const int  row    = in_ksp ? ((idx / 80) % LN)
                               : (((idx - n4m) / 80) % LN);

    // wait for mask_kernel's writes to be visible
    cudaGridDependencySynchronize();

    if (idx >= n4tot) return;
    const float m = d_mask[row];       // exactly 0.0f or 1.0f
    if (in_ksp) {
        if (m != 0.0f) {
            __stcs(&out[idx], __ldcs(&ksp[idx]));
        } else {
            __stcs(&out[idx], make_float4(0.f, 0.f, 0.f, 0.f));
        }
    } else {
        __stcs(&out[idx], make_float4(m, m, m, m));
    }
}

extern "C" void kernel_launch(void* const* d_in, const int* in_sizes, int n_in,
                              void* d_out, int out_size) {
    const float* kspace   = (const float*)d_in[0];  // (256,2,320,320)
    const float* sparsity = (const float*)d_in[1];  // scalar
    const float* logits   = (const float*)d_in[2];  // (320,)

    // Host-side threefry split chain (independent of device inputs).
    // JAX partitionable split: new_key = TF(key,0,0), sub = TF(key,0,1).
    SubKeys subs;
    {
        uint32_t k0 = 0u, k1 = 42u;   // jax.random.key(42)
        for (int i = 0; i < NPROBE; i++) {
            uint32_t s0, s1, n0, n1;
            threefry2x32(k0, k1, 0u, 1u, s0, s1);
            threefry2x32(k0, k1, 0u, 0u, n0, n1);
            subs.s[i] = make_uint2(s0, s1);
            k0 = n0; k1 = n1;
        }
        subs.tail = make_uint2(k0, k1);
    }

    mask_kernel<<<NPROBE, LN>>>(logits, sparsity, subs);

    int n4m   = in_sizes[0] / 4;
    int n4tot = out_size / 4;
    int threads = 256;
    int blocks  = (n4tot + threads - 1) / threads;

    cudaLaunchConfig_t cfg = {};
    cfg.gridDim  = dim3((unsigned)blocks, 1, 1);
    cfg.blockDim = dim3((unsigned)threads, 1, 1);
    cfg.dynamicSmemBytes = 0;
    cfg.stream = 0;
    cudaLaunchAttribute attr[1];
    attr[0].id = cudaLaunchAttributeProgrammaticStreamSerialization;
    attr[0].val.programmaticStreamSerializationAllowed = 1;
    cfg.attrs = attr;
    cfg.numAttrs = 1;
    cudaLaunchKernelEx(&cfg, apply_mask_kernel,
                       (const float4*)kspace, (float4*)d_out, n4m, n4tot);
}